// round 8
// baseline (speedup 1.0000x reference)
#include <cuda_runtime.h>

#define D        64
#define KCODES   1024
#define BR       128
#define BK       128
#define NTHREADS 256
#define PAD      65    // sX row pad -> conflict-free strided LDS
#define EPAD     130   // sEt row stride in floats (even -> LDS.64 aligned)

typedef unsigned long long ull;

// scratch (no allocation allowed): codebook norms + loss accumulator
__device__ float g_e[KCODES];
__device__ float g_loss;

// smem layout (dynamic):
//   sX   [BR*PAD]  floats   (row-major X tile)
//   sEt  [D*EPAD]  floats   (TRANSPOSED codebook tile: [d][code])
//   sH   [BK]      floats   (enorm tile)
//   sXn  [BR]      floats   (row norms, bit-matched sequential order)
//   sIdx [BR]      ints
//   sRed [8]       floats
#define SMEM_BYTES ((BR*PAD + D*EPAD + BK + BR)*4 + BR*4 + 8*4)

__device__ __forceinline__ void ffma2(ull& d, ull a, ull b) {
    asm("fma.rn.f32x2 %0, %1, %2, %0;" : "+l"(d) : "l"(a), "l"(b));
}
__device__ __forceinline__ ull pack2(float lo, float hi) {
    ull r;
    asm("mov.b64 %0, {%1, %2};" : "=l"(r) : "f"(lo), "f"(hi));
    return r;
}
__device__ __forceinline__ void unpack2(ull v, float& lo, float& hi) {
    asm("mov.b64 {%0, %1}, %2;" : "=f"(lo), "=f"(hi) : "l"(v));
}

// enorm_k = sum_d fl(e*e), sequential d=0..63, mul/add separately rounded
// (replicates the reference's elementwise-square + sequential reduce)
__global__ void vq_prep(const float* __restrict__ cb) {
    int k = blockIdx.x * blockDim.x + threadIdx.x;
    if (k == 0) g_loss = 0.0f;
    if (k < KCODES) {
        const float* p = cb + k * D;
        float s = 0.0f;
        #pragma unroll
        for (int i = 0; i < D; ++i)
            s = __fadd_rn(s, __fmul_rn(p[i], p[i]));
        g_e[k] = s;
    }
}

extern __shared__ float smem_dyn[];

__global__ __launch_bounds__(NTHREADS, 2) void vq_main(
    const float* __restrict__ x, const float* __restrict__ cb,
    float* __restrict__ out, int nrows)
{
    float* sX   = smem_dyn;                 // BR*PAD
    float* sEt  = sX + BR * PAD;            // D*EPAD
    float* sH   = sEt + D * EPAD;           // BK
    float* sXn  = sH + BK;                  // BR
    int*   sIdx = (int*)(sXn + BR);         // BR
    float* sRed = (float*)(sIdx + BR);      // 8

    const int tid = threadIdx.x;
    const int tx  = tid & 15;               // code-pair group
    const int ty  = tid >> 4;               // row group
    const int rowbase = blockIdx.x * BR;
    const int rows_here = min(BR, nrows - rowbase);

    // ---- load X tile [BR x D] (float4 global -> padded smem) ----
    {
        const float4* gx = (const float4*)(x + (size_t)rowbase * D);
        for (int e = tid; e < BR * D / 4; e += NTHREADS) {
            int r = e >> 4;             // 16 float4 per row
            int d = (e & 15) << 2;
            float4 v;
            if (r < rows_here) v = gx[e];
            else               v = make_float4(0.f, 0.f, 0.f, 0.f);
            float* p = sX + r * PAD + d;
            p[0] = v.x; p[1] = v.y; p[2] = v.z; p[3] = v.w;
        }
    }
    __syncthreads();

    // ---- row norms, bit-matched: sequential d=0..63, rounded mul then add ----
    if (tid < BR) {
        const float* p = sX + tid * PAD;
        float s = 0.0f;
        #pragma unroll
        for (int i = 0; i < D; ++i)
            s = __fadd_rn(s, __fmul_rn(p[i], p[i]));
        sXn[tid] = s;
    }

    float bestv[8];
    int   besti[8];
    #pragma unroll
    for (int i = 0; i < 8; ++i) { bestv[i] = 3.4e38f; besti[i] = 0; }

    // ---- K loop over codebook tiles ----
    for (int t = 0; t < KCODES / BK; ++t) {
        __syncthreads();
        {
            // load tile coalesced, write TRANSPOSED: sEt[d][c]
            const float4* ge = (const float4*)(cb + (size_t)t * BK * D);
            for (int e = tid; e < BK * D / 4; e += NTHREADS) {
                float4 v = ge[e];
                int c = e >> 4;             // code 0..127
                int d = (e & 15) << 2;
                sEt[(d + 0) * EPAD + c] = v.x;
                sEt[(d + 1) * EPAD + c] = v.y;
                sEt[(d + 2) * EPAD + c] = v.z;
                sEt[(d + 3) * EPAD + c] = v.w;
            }
            if (tid < BK) sH[tid] = g_e[t * BK + tid];
        }
        __syncthreads();

        // packed-f32x2 dot accumulation: each 64-bit acc holds codes
        // (2*tx+32*jp, +1) for one row. Per-lane FFMA2 is IEEE-rn fp32 FMA,
        // ascending-d single-accumulator chain -> bitwise-matches the
        // reference GEMM's per-element k-chain.
        ull acc2[8][4];
        #pragma unroll
        for (int i = 0; i < 8; ++i)
            #pragma unroll
            for (int jp = 0; jp < 4; ++jp) acc2[i][jp] = 0ull;

        #pragma unroll 4
        for (int d = 0; d < D; ++d) {
            ull ev2[4], xv2[8];
            const ull* pe = (const ull*)(sEt + EPAD * d);
            #pragma unroll
            for (int jp = 0; jp < 4; ++jp) ev2[jp] = pe[tx + 16 * jp];
            #pragma unroll
            for (int i = 0; i < 8; ++i) {
                float v = sX[(ty + 16 * i) * PAD + d];
                xv2[i] = pack2(v, v);
            }
            #pragma unroll
            for (int i = 0; i < 8; ++i)
                #pragma unroll
                for (int jp = 0; jp < 4; ++jp)
                    ffma2(acc2[i][jp], xv2[i], ev2[jp]);
        }

        // fold: dist = fl(fl(xnorm + enorm) - fl(2*mm)), even code before odd,
        // ascending jp; strict '<' keeps the lowest index on quantized ties.
        #pragma unroll
        for (int jp = 0; jp < 4; ++jp) {
            int   cb0  = 2 * tx + 32 * jp;
            float en0  = sH[cb0];
            float en1  = sH[cb0 + 1];
            int   code = t * BK + cb0;
            #pragma unroll
            for (int i = 0; i < 8; ++i) {
                float m0, m1;
                unpack2(acc2[i][jp], m0, m1);
                float xn = sXn[ty + 16 * i];
                float d0 = __fsub_rn(__fadd_rn(xn, en0), __fmul_rn(2.0f, m0));
                if (d0 < bestv[i]) { bestv[i] = d0; besti[i] = code; }
                float d1 = __fsub_rn(__fadd_rn(xn, en1), __fmul_rn(2.0f, m1));
                if (d1 < bestv[i]) { bestv[i] = d1; besti[i] = code + 1; }
            }
        }
    }

    // ---- reduce argmin across the 16 code-group lanes (xor over tx bits) ----
    #pragma unroll
    for (int i = 0; i < 8; ++i) {
        #pragma unroll
        for (int m = 1; m < 16; m <<= 1) {
            float ov = __shfl_xor_sync(0xffffffffu, bestv[i], m);
            int   oi = __shfl_xor_sync(0xffffffffu, besti[i], m);
            if (ov < bestv[i] || (ov == bestv[i] && oi < besti[i])) {
                bestv[i] = ov; besti[i] = oi;
            }
        }
        if (tx == 0) sIdx[ty + 16 * i] = besti[i];
    }
    __syncthreads();

    // ---- epilogue: gather codewords, write output, accumulate loss ----
    float lsum = 0.0f;
    for (int e = tid; e < BR * D; e += NTHREADS) {
        int r = e >> 6;
        int d = e & 63;
        if (r < rows_here) {
            int   k  = sIdx[r];
            float q  = __ldg(cb + (size_t)k * D + d);
            float xv = sX[r * PAD + d];
            out[(size_t)(rowbase + r) * D + d] = q;
            float df = q - xv;
            lsum += df * df;
        }
    }
    #pragma unroll
    for (int m = 16; m >= 1; m >>= 1)
        lsum += __shfl_xor_sync(0xffffffffu, lsum, m);
    if ((tid & 31) == 0) sRed[tid >> 5] = lsum;
    __syncthreads();
    if (tid < 8) {
        float v = sRed[tid];
        #pragma unroll
        for (int m = 4; m >= 1; m >>= 1)
            v += __shfl_xor_sync(0x000000ffu, v, m);
        if (tid == 0) atomicAdd(&g_loss, v);
    }
}

__global__ void vq_finish(float* out, int pos, float inv_n) {
    // vq_loss = codebook_loss + 0.25*commitment_loss; both equal mean((q-x)^2)
    out[pos] = 1.25f * g_loss * inv_n;
}

extern "C" void kernel_launch(void* const* d_in, const int* in_sizes, int n_in,
                              void* d_out, int out_size) {
    const float* x  = (const float*)d_in[0];
    const float* cb = (const float*)d_in[1];
    float* out = (float*)d_out;

    const int nrows = in_sizes[0] / D;              // 65536
    const int nblocks = (nrows + BR - 1) / BR;      // 512

    cudaFuncSetAttribute(vq_main, cudaFuncAttributeMaxDynamicSharedMemorySize,
                         SMEM_BYTES);

    vq_prep<<<(KCODES + 127) / 128, 128>>>(cb);
    vq_main<<<nblocks, NTHREADS, SMEM_BYTES>>>(x, cb, out, nrows);
    vq_finish<<<1, 1>>>(out, out_size - 1, 1.0f / (float)((size_t)nrows * D));
}

// round 11
// speedup vs baseline: 1.1433x; 1.1433x over previous
#include <cuda_runtime.h>
#include <cuda_bf16.h>
#include <cstdint>

#define KCODES   1024
#define DIM      64
#define W_MARGIN 8e-5f
#define SBASE    0x3E800000u     // bits of 0.25f

// ---------- device scratch (static, no allocation) ----------
__device__ float g_e[KCODES];                      // exact ref-chain enorms
__device__ __align__(16) __nv_bfloat16 g_bpk[KCODES * 144]; // packed B: (-2e)hi|(-2e)lo|c0 splits
__device__ int   g_bidx[65536];
__device__ int   g_flag[65536];
__device__ int   g_nflag;
__device__ float g_loss;

__device__ __forceinline__ uint32_t smem_u32(const void* p) {
    uint32_t a;
    asm("{ .reg .u64 t; cvta.to.shared.u64 t, %1; cvt.u32.u64 %0, t; }"
        : "=r"(a) : "l"(p));
    return a;
}
__device__ __forceinline__ void ldsm4(uint32_t* r, uint32_t a) {
    asm volatile("ldmatrix.sync.aligned.m8n8.x4.shared.b16 {%0,%1,%2,%3}, [%4];"
        : "=r"(r[0]), "=r"(r[1]), "=r"(r[2]), "=r"(r[3]) : "r"(a));
}
__device__ __forceinline__ void mma_bf16(float* d, const uint32_t* a,
                                         uint32_t b0, uint32_t b1) {
    asm volatile(
        "mma.sync.aligned.m16n8k16.row.col.f32.bf16.bf16.f32 "
        "{%0,%1,%2,%3}, {%4,%5,%6,%7}, {%8,%9}, {%0,%1,%2,%3};"
        : "+f"(d[0]), "+f"(d[1]), "+f"(d[2]), "+f"(d[3])
        : "r"(a[0]), "r"(a[1]), "r"(a[2]), "r"(a[3]), "r"(b0), "r"(b1));
}

// ============ prep: exact enorm chain + packed bf16 B operand ============
__global__ void vq_prep(const float* __restrict__ cb) {
    int k = blockIdx.x * 128 + threadIdx.x;
    if (k == 0) { g_loss = 0.0f; g_nflag = 0; }
    if (k < KCODES) {
        const float* p = cb + k * DIM;
        __nv_bfloat16* row = g_bpk + k * 144;
        float s = 0.0f;
        #pragma unroll
        for (int i = 0; i < DIM; ++i) {
            float v = p[i];
            s = __fadd_rn(s, __fmul_rn(v, v));     // bit-matched ref chain
            float m2 = -2.0f * v;                  // exact
            __nv_bfloat16 h = __float2bfloat16(m2);
            row[i]      = h;
            row[64 + i] = __float2bfloat16(m2 - __bfloat162float(h));
        }
        g_e[k] = s;
        float c0 = 0.5f + s;
        __nv_bfloat16 h1 = __float2bfloat16(c0);
        float r1 = c0 - __bfloat162float(h1);
        __nv_bfloat16 h2 = __float2bfloat16(r1);
        float r2 = r1 - __bfloat162float(h2);
        row[128] = h1; row[129] = h2; row[130] = __float2bfloat16(r2);
        #pragma unroll
        for (int i = 131; i < 144; ++i) row[i] = __float2bfloat16(0.0f);
    }
}

// ============ stage 1: HMMA approx scores + min2 keys + margin flags ============
#define ASTRIDE  304        // bytes per smem row (152 bf16; 19x16B -> conflict-free ldmatrix)
#define SA_OFF   0
#define SB_OFF   38912
#define SM_OFF   77824
#define SM_TOTAL 81920

extern __shared__ char smx[];
__global__ __launch_bounds__(256, 2) void vq_main(const float* __restrict__ x) {
    const uint32_t sbase = smem_u32(smx);
    const int tid = threadIdx.x, w = tid >> 5, lane = tid & 31;
    const int wr = (w & 3) * 32;          // warp row base (M=32 per warp)
    const int wc = (w >> 2) * 64;         // warp col base (N=64 per warp)
    const int rowbase = blockIdx.x * 128;

    // ---- A tile: x -> hi/lo bf16 splits + constant columns ----
    {
        const float4* gx = (const float4*)(x + (size_t)rowbase * DIM);
        #pragma unroll
        for (int i = 0; i < 8; ++i) {
            int e = tid + i * 256;
            int r = e >> 4, c = (e & 15) << 2;
            float4 v = gx[e];
            char* rp = smx + SA_OFF + r * ASTRIDE;
            __nv_bfloat162 h0, h1, l0, l1;
            h0.x = __float2bfloat16(v.x); h0.y = __float2bfloat16(v.y);
            h1.x = __float2bfloat16(v.z); h1.y = __float2bfloat16(v.w);
            l0.x = __float2bfloat16(v.x - __bfloat162float(h0.x));
            l0.y = __float2bfloat16(v.y - __bfloat162float(h0.y));
            l1.x = __float2bfloat16(v.z - __bfloat162float(h1.x));
            l1.y = __float2bfloat16(v.w - __bfloat162float(h1.y));
            *(__nv_bfloat162*)(rp + c * 2)            = h0;
            *(__nv_bfloat162*)(rp + c * 2 + 4)        = h1;
            *(__nv_bfloat162*)(rp + (64 + c) * 2)     = l0;
            *(__nv_bfloat162*)(rp + (64 + c) * 2 + 4) = l1;
        }
        if (tid < 128) {   // const cols 128..143: 1,1,1,0,...,0
            char* rp = smx + SA_OFF + tid * ASTRIDE + 256;
            __nv_bfloat16 one = __float2bfloat16(1.0f), zer = __float2bfloat16(0.0f);
            __nv_bfloat162 v;
            v.x = one; v.y = one; *(__nv_bfloat162*)(rp)     = v;
            v.x = one; v.y = zer; *(__nv_bfloat162*)(rp + 4) = v;
            v.x = zer; v.y = zer;
            #pragma unroll
            for (int i = 2; i < 8; ++i) *(__nv_bfloat162*)(rp + i * 4) = v;
        }
    }

    // ldmatrix lane addresses (canonical m16n8k16 fragment addressing)
    const uint32_t aAddr = sbase + SA_OFF + (wr + (lane & 15)) * ASTRIDE + ((lane >> 4) << 4);
    const uint32_t bAddr = sbase + SB_OFF +
        (wc + (lane & 7) + ((lane >> 3) & 1) * 8) * ASTRIDE + ((lane >> 4) << 4);

    const int brow = tid >> 1, bpart = tid & 1;    // B loader: 2 threads/row, 9 uint4 each

    uint32_t t1[4] = {~0u, ~0u, ~0u, ~0u};
    uint32_t t2[4] = {~0u, ~0u, ~0u, ~0u};
    uint32_t tl[4] = {0, 0, 0, 0};
    const uint32_t KC = (uint32_t)(wc + 2 * (lane & 3)) + 0xC0000000u; // folds -(SBASE<<7) mod 2^32

    const int AK[13] = {0,32,64,96,   0,32,64,96, 128,160,192,224, 256}; // byte k-offsets
    const int BK[13] = {0,32,64,96, 128,160,192,224, 0,32,64,96,   256};

    for (int t = 0; t < 8; ++t) {
        __syncthreads();                           // prior tile's ldmatrix done
        {
            const uint4* gb = (const uint4*)(g_bpk + (size_t)(t * 128 + brow) * 144) + bpart * 9;
            uint4* sb = (uint4*)(smx + SB_OFF + brow * ASTRIDE + bpart * 144);
            #pragma unroll
            for (int c = 0; c < 9; ++c) sb[c] = gb[c];
        }
        __syncthreads();

        float d[2][8][4];
        #pragma unroll
        for (int mf = 0; mf < 2; ++mf)
            #pragma unroll
            for (int nb = 0; nb < 8; ++nb)
                #pragma unroll
                for (int j = 0; j < 4; ++j) d[mf][nb][j] = 0.0f;

        #pragma unroll
        for (int s = 0; s < 13; ++s) {
            uint32_t a0[4], a1[4];
            ldsm4(a0, aAddr + AK[s]);
            ldsm4(a1, aAddr + 16 * ASTRIDE + AK[s]);
            #pragma unroll
            for (int nbp = 0; nbp < 4; ++nbp) {
                uint32_t bb[4];
                ldsm4(bb, bAddr + nbp * 16 * ASTRIDE + BK[s]);
                mma_bf16(d[0][2 * nbp],     a0, bb[0], bb[2]);
                mma_bf16(d[0][2 * nbp + 1], a0, bb[1], bb[3]);
                mma_bf16(d[1][2 * nbp],     a1, bb[0], bb[2]);
                mma_bf16(d[1][2 * nbp + 1], a1, bb[1], bb[3]);
            }
        }

        // fold scores (D already = c0 - 2*dot) into per-slot min1/min2 keys
        uint32_t pre[4] = {t1[0], t1[1], t1[2], t1[3]};
        #pragma unroll
        for (int mf = 0; mf < 2; ++mf)
            #pragma unroll
            for (int nb = 0; nb < 8; ++nb)
                #pragma unroll
                for (int j = 0; j < 4; ++j) {
                    float sc = fminf(fmaxf(d[mf][nb][j], 0.25f), 0.75f); // self-flag clamp
                    uint32_t key = __float_as_uint(sc) * 128u + KC
                                 + (uint32_t)(nb * 8 + (j & 1));
                    int sl = mf * 2 + (j >> 1);
                    t2[sl] = min(t2[sl], max(t1[sl], key));
                    t1[sl] = min(t1[sl], key);
                }
        #pragma unroll
        for (int sl = 0; sl < 4; ++sl)
            if (t1[sl] != pre[sl]) tl[sl] = (uint32_t)t;
    }

    // in-warp merge across the 4 col-lanes (xor 1, 2)
    #pragma unroll
    for (int m = 1; m <= 2; m <<= 1) {
        #pragma unroll
        for (int sl = 0; sl < 4; ++sl) {
            uint32_t o1 = __shfl_xor_sync(~0u, t1[sl], m);
            uint32_t ot = __shfl_xor_sync(~0u, tl[sl], m);
            uint32_t o2 = __shfl_xor_sync(~0u, t2[sl], m);
            uint32_t n2 = min(min(t2[sl], o2), max(t1[sl], o1));
            if (o1 < t1[sl]) { t1[sl] = o1; tl[sl] = ot; }
            t2[sl] = n2;
        }
    }
    uint32_t* sM = (uint32_t*)(smx + SM_OFF);
    if ((lane & 3) == 0) {
        #pragma unroll
        for (int sl = 0; sl < 4; ++sl) {
            int r = wr + (sl >> 1) * 16 + (sl & 1) * 8 + (lane >> 2);
            uint32_t* p = sM + r * 8 + (w >> 2) * 3;
            p[0] = t1[sl]; p[1] = tl[sl]; p[2] = t2[sl];
        }
    }
    __syncthreads();
    if (tid < 128) {   // merge the two col-halves, emit idx + margin flag
        uint32_t* p = sM + tid * 8;
        uint32_t a1 = p[0], at = p[1], a2 = p[2];
        uint32_t b1 = p[3], bt = p[4], b2 = p[5];
        uint32_t n2 = min(min(a2, b2), max(a1, b1));
        uint32_t n1 = a1, nt = at;
        if (b1 < a1) { n1 = b1; nt = bt; }
        g_bidx[rowbase + tid] = (int)(nt * 128u + (n1 & 127u));
        float s1 = __uint_as_float(SBASE + (n1 >> 7));
        float s2 = __uint_as_float(SBASE + (n2 >> 7));
        if (s2 - s1 < W_MARGIN) g_flag[atomicAdd(&g_nflag, 1)] = rowbase + tid;
    }
}

// ============ stage 2: exact bit-matched rescan of flagged rows ============
__global__ __launch_bounds__(256) void vq_fix(const float* __restrict__ x,
                                              const float* __restrict__ cb) {
    __shared__ float sX[16 * 65];
    __shared__ float sE[128 * 65];
    __shared__ float sH[128];
    __shared__ float sXn[16];
    __shared__ int   sRow[16];
    const int tid = threadIdx.x, tx = tid & 15, ty = tid >> 4;
    const int nf = g_nflag;

    for (int base = blockIdx.x * 16; base < nf; base += gridDim.x * 16) {
        int cnt = min(16, nf - base);
        __syncthreads();
        if (tid < 16) sRow[tid] = g_flag[base + min(tid, cnt - 1)];
        __syncthreads();
        {
            int r = tid >> 4, d = (tid & 15) * 4;
            float4 v = *(const float4*)(x + (size_t)sRow[r] * DIM + d);
            float* p = sX + r * 65 + d;
            p[0] = v.x; p[1] = v.y; p[2] = v.z; p[3] = v.w;
        }
        __syncthreads();
        if (tid < 16) {
            const float* p = sX + tid * 65;
            float s = 0.0f;
            #pragma unroll
            for (int i = 0; i < DIM; ++i)
                s = __fadd_rn(s, __fmul_rn(p[i], p[i]));
            sXn[tid] = s;
        }
        float bestv = 3.4e38f; int besti = 0;
        for (int t = 0; t < 8; ++t) {
            __syncthreads();
            #pragma unroll
            for (int i = 0; i < 8; ++i) {
                int e = tid + i * 256;
                int c = e >> 4, d = (e & 15) * 4;
                float4 v = *(const float4*)(cb + (size_t)(t * 128 + c) * DIM + d);
                float* p = sE + c * 65 + d;
                p[0] = v.x; p[1] = v.y; p[2] = v.z; p[3] = v.w;
            }
            if (tid < 128) sH[tid] = g_e[t * 128 + tid];
            __syncthreads();
            float acc[8];
            #pragma unroll
            for (int j = 0; j < 8; ++j) acc[j] = 0.0f;
            #pragma unroll 4
            for (int d = 0; d < DIM; ++d) {
                float xv = sX[ty * 65 + d];
                #pragma unroll
                for (int j = 0; j < 8; ++j) acc[j] += xv * sE[(tx + 16 * j) * 65 + d];
            }
            #pragma unroll
            for (int j = 0; j < 8; ++j) {
                int cg = tx + 16 * j;
                float dist = __fsub_rn(__fadd_rn(sXn[ty], sH[cg]),
                                       __fmul_rn(2.0f, acc[j]));
                if (dist < bestv) { bestv = dist; besti = t * 128 + cg; }
            }
        }
        #pragma unroll
        for (int m = 1; m < 16; m <<= 1) {
            float ov = __shfl_xor_sync(0xffffffffu, bestv, m);
            int   oi = __shfl_xor_sync(0xffffffffu, besti, m);
            if (ov < bestv || (ov == bestv && oi < besti)) { bestv = ov; besti = oi; }
        }
        if (tx == 0 && ty < cnt) g_bidx[sRow[ty]] = besti;
    }
}

// ============ output gather + loss ============
__global__ __launch_bounds__(256) void vq_out(const float* __restrict__ x,
                                              const float* __restrict__ cb,
                                              float* __restrict__ out) {
    __shared__ float sRed[8];
    const int tid = threadIdx.x;
    const int rowbase = blockIdx.x * 128;
    float lsum = 0.0f;
    #pragma unroll
    for (int i = 0; i < 8; ++i) {
        int e = tid + i * 256;
        int r = e >> 4, d = (e & 15) * 4;
        int grow = rowbase + r;
        int k = g_bidx[grow];
        float4 q  = __ldg((const float4*)(cb + (size_t)k * DIM + d));
        float4 xv = __ldg((const float4*)(x + (size_t)grow * DIM + d));
        *(float4*)(out + (size_t)grow * DIM + d) = q;
        float a = q.x - xv.x, b = q.y - xv.y, c = q.z - xv.z, dd = q.w - xv.w;
        lsum += a * a + b * b + c * c + dd * dd;
    }
    #pragma unroll
    for (int m = 16; m >= 1; m >>= 1)
        lsum += __shfl_xor_sync(0xffffffffu, lsum, m);
    if ((tid & 31) == 0) sRed[tid >> 5] = lsum;
    __syncthreads();
    if (tid < 8) {
        float v = sRed[tid];
        #pragma unroll
        for (int m = 4; m >= 1; m >>= 1)
            v += __shfl_xor_sync(0x000000ffu, v, m);
        if (tid == 0) atomicAdd(&g_loss, v);
    }
}

__global__ void vq_finish(float* out, int pos, float inv_n) {
    out[pos] = 1.25f * g_loss * inv_n;
}

extern "C" void kernel_launch(void* const* d_in, const int* in_sizes, int n_in,
                              void* d_out, int out_size) {
    const float* x  = (const float*)d_in[0];
    const float* cb = (const float*)d_in[1];
    float* out = (float*)d_out;
    const int nrows = in_sizes[0] / DIM;       // 65536
    const int nblocks = nrows / 128;           // 512

    cudaFuncSetAttribute(vq_main, cudaFuncAttributeMaxDynamicSharedMemorySize,
                         SM_TOTAL);

    vq_prep<<<8, 128>>>(cb);
    vq_main<<<nblocks, 256, SM_TOTAL>>>(x);
    vq_fix<<<96, 256>>>(x, cb);
    vq_out<<<nblocks, 256>>>(x, cb, out);
    vq_finish<<<1, 1>>>(out, out_size - 1, 1.0f / (float)((size_t)nrows * DIM));
}

// round 13
// speedup vs baseline: 1.4590x; 1.2761x over previous
#include <cuda_runtime.h>
#include <cuda_bf16.h>
#include <cstdint>

#define KCODES   1024
#define DIM      64
#define W_MARGIN 8e-5f
#define SBASE    0x3E800000u     // bits of 0.25f

// ---------- device scratch (static, no allocation) ----------
__device__ float g_e[KCODES];                       // exact ref-chain enorms
__device__ __align__(16) __nv_bfloat16 g_bpk[KCODES * 152]; // (-2e)hi|(-2e)lo|c0splits|pad
__device__ int   g_flag[65536];
__device__ int   g_nflag;
__device__ float g_loss;

__device__ __forceinline__ uint32_t smem_u32(const void* p) {
    uint32_t a;
    asm("{ .reg .u64 t; cvta.to.shared.u64 t, %1; cvt.u32.u64 %0, t; }"
        : "=r"(a) : "l"(p));
    return a;
}
__device__ __forceinline__ void ldsm4(uint32_t* r, uint32_t a) {
    asm volatile("ldmatrix.sync.aligned.m8n8.x4.shared.b16 {%0,%1,%2,%3}, [%4];"
        : "=r"(r[0]), "=r"(r[1]), "=r"(r[2]), "=r"(r[3]) : "r"(a));
}
__device__ __forceinline__ void mma_bf16(float* d, const uint32_t* a,
                                         uint32_t b0, uint32_t b1) {
    asm volatile(
        "mma.sync.aligned.m16n8k16.row.col.f32.bf16.bf16.f32 "
        "{%0,%1,%2,%3}, {%4,%5,%6,%7}, {%8,%9}, {%0,%1,%2,%3};"
        : "+f"(d[0]), "+f"(d[1]), "+f"(d[2]), "+f"(d[3])
        : "r"(a[0]), "r"(a[1]), "r"(a[2]), "r"(a[3]), "r"(b0), "r"(b1));
}
__device__ __forceinline__ void cpasync16(uint32_t sdst, const void* gsrc) {
    asm volatile("cp.async.cg.shared.global [%0], [%1], 16;"
                 :: "r"(sdst), "l"(gsrc) : "memory");
}

// ============ prep: exact enorm chain + packed bf16 B operand ============
__global__ void vq_prep(const float* __restrict__ cb) {
    int k = blockIdx.x * 128 + threadIdx.x;
    if (k == 0) { g_loss = 0.0f; g_nflag = 0; }
    if (k < KCODES) {
        const float4* p4 = (const float4*)(cb + k * DIM);
        __nv_bfloat16* row = g_bpk + k * 152;
        float s = 0.0f;
        #pragma unroll
        for (int q = 0; q < 16; ++q) {
            float4 v = p4[q];
            float e0 = v.x, e1 = v.y, e2 = v.z, e3 = v.w;
            s = __fadd_rn(s, __fmul_rn(e0, e0));
            s = __fadd_rn(s, __fmul_rn(e1, e1));
            s = __fadd_rn(s, __fmul_rn(e2, e2));
            s = __fadd_rn(s, __fmul_rn(e3, e3));
            float m0 = -2.0f * e0, m1 = -2.0f * e1, m2 = -2.0f * e2, m3 = -2.0f * e3;
            __nv_bfloat162 h01, h23, l01, l23;
            h01.x = __float2bfloat16(m0); h01.y = __float2bfloat16(m1);
            h23.x = __float2bfloat16(m2); h23.y = __float2bfloat16(m3);
            l01.x = __float2bfloat16(m0 - __bfloat162float(h01.x));
            l01.y = __float2bfloat16(m1 - __bfloat162float(h01.y));
            l23.x = __float2bfloat16(m2 - __bfloat162float(h23.x));
            l23.y = __float2bfloat16(m3 - __bfloat162float(h23.y));
            *(__nv_bfloat162*)(row + q * 4)          = h01;
            *(__nv_bfloat162*)(row + q * 4 + 2)      = h23;
            *(__nv_bfloat162*)(row + 64 + q * 4)     = l01;
            *(__nv_bfloat162*)(row + 64 + q * 4 + 2) = l23;
        }
        g_e[k] = s;
        float c0 = 0.5f + s;
        __nv_bfloat16 h1 = __float2bfloat16(c0);
        float r1 = c0 - __bfloat162float(h1);
        __nv_bfloat16 h2 = __float2bfloat16(r1);
        float r2 = r1 - __bfloat162float(h2);
        row[128] = h1; row[129] = h2; row[130] = __float2bfloat16(r2);
        #pragma unroll
        for (int i = 131; i < 136; ++i) row[i] = __float2bfloat16(0.0f);
        *(uint4*)(row + 136) = make_uint4(0, 0, 0, 0);
        *(uint4*)(row + 144) = make_uint4(0, 0, 0, 0);
    }
}

// ============ stage 1: HMMA scores (pipelined) + min2 + fused output ============
#define ASTRIDE  304        // 19x16B rows -> conflict-free ldmatrix
#define SA       0          // 128*304 = 38912
#define SB       38912      // 2 stages x 64*304 = 19456
#define SBSTG    19456
#define SIDX     77824      // int[128]
#define SRED     78336      // float[8]
#define SM_TOTAL 78400

extern __shared__ char smx[];
__global__ __launch_bounds__(256, 2) void vq_main(
    const float* __restrict__ x, const float* __restrict__ cb,
    float* __restrict__ out)
{
    const uint32_t sbase = smem_u32(smx);
    const int tid = threadIdx.x, w = tid >> 5, lane = tid & 31;
    const int rowbase = blockIdx.x * 128;
    int* sIdx = (int*)(smx + SIDX);

    // prologue: async-load B half-tile 0 into stage 0
    {
        #pragma unroll
        for (int i = 0; i < 5; ++i) {
            int c = tid + i * 256;
            if (c < 1216) {
                int r = c / 19, cc = c % 19;
                cpasync16(sbase + SB + r * ASTRIDE + cc * 16,
                          (const char*)g_bpk + ((size_t)r * 152 + cc * 8) * 2);
            }
        }
        asm volatile("cp.async.commit_group;" ::: "memory");
    }

    // ---- A tile: x -> hi/lo bf16 splits + constant columns ----
    {
        const float4* gx = (const float4*)(x + (size_t)rowbase * DIM);
        #pragma unroll
        for (int i = 0; i < 8; ++i) {
            int e = tid + i * 256;
            int r = e >> 4, c = (e & 15) << 2;
            float4 v = gx[e];
            char* rp = smx + SA + r * ASTRIDE;
            __nv_bfloat162 h0, h1, l0, l1;
            h0.x = __float2bfloat16(v.x); h0.y = __float2bfloat16(v.y);
            h1.x = __float2bfloat16(v.z); h1.y = __float2bfloat16(v.w);
            l0.x = __float2bfloat16(v.x - __bfloat162float(h0.x));
            l0.y = __float2bfloat16(v.y - __bfloat162float(h0.y));
            l1.x = __float2bfloat16(v.z - __bfloat162float(h1.x));
            l1.y = __float2bfloat16(v.w - __bfloat162float(h1.y));
            *(__nv_bfloat162*)(rp + c * 2)            = h0;
            *(__nv_bfloat162*)(rp + c * 2 + 4)        = h1;
            *(__nv_bfloat162*)(rp + (64 + c) * 2)     = l0;
            *(__nv_bfloat162*)(rp + (64 + c) * 2 + 4) = l1;
        }
        if (tid < 128) {   // const cols 128..143: 1,1,1,0,...,0
            char* rp = smx + SA + tid * ASTRIDE + 256;
            __nv_bfloat16 one = __float2bfloat16(1.0f), zer = __float2bfloat16(0.0f);
            __nv_bfloat162 v;
            v.x = one; v.y = one; *(__nv_bfloat162*)(rp)     = v;
            v.x = one; v.y = zer; *(__nv_bfloat162*)(rp + 4) = v;
            v.x = zer; v.y = zer;
            #pragma unroll
            for (int i = 2; i < 8; ++i) *(__nv_bfloat162*)(rp + i * 4) = v;
        }
    }

    const uint32_t aAddr = sbase + SA + (w * 16 + (lane & 15)) * ASTRIDE + ((lane >> 4) << 4);
    const uint32_t bAddr0 = sbase + SB +
        ((lane & 7) + ((lane >> 3) & 1) * 8) * ASTRIDE + ((lane >> 4) << 4);

    uint32_t t1[2] = {~0u, ~0u}, t2[2] = {~0u, ~0u};
    int th[2] = {0, 0};
    const uint32_t KC = 0x60000000u + 2 * (lane & 3);  // folds -(SBASE<<6) mod 2^32

    const int AK[13] = {0,32,64,96,   0,32,64,96, 128,160,192,224, 256};
    const int BK[13] = {0,32,64,96, 128,160,192,224, 0,32,64,96,   256};

    for (int h = 0; h < 16; ++h) {
        asm volatile("cp.async.wait_group 0;" ::: "memory");
        __syncthreads();   // B(h) ready; all compute on stage (h+1)&1 done
        if (h < 15) {
            int st = (h + 1) & 1;
            #pragma unroll
            for (int i = 0; i < 5; ++i) {
                int c = tid + i * 256;
                if (c < 1216) {
                    int r = c / 19, cc = c % 19;
                    cpasync16(sbase + SB + st * SBSTG + r * ASTRIDE + cc * 16,
                              (const char*)g_bpk +
                              ((size_t)((h + 1) * 64 + r) * 152 + cc * 8) * 2);
                }
            }
            asm volatile("cp.async.commit_group;" ::: "memory");
        }

        const uint32_t bAddr = bAddr0 + (h & 1) * SBSTG;
        float d[8][4];
        #pragma unroll
        for (int nb = 0; nb < 8; ++nb)
            #pragma unroll
            for (int j = 0; j < 4; ++j) d[nb][j] = 0.0f;

        #pragma unroll
        for (int s = 0; s < 13; ++s) {
            uint32_t a0[4];
            ldsm4(a0, aAddr + AK[s]);
            #pragma unroll
            for (int nbp = 0; nbp < 4; ++nbp) {
                uint32_t bb[4];
                ldsm4(bb, bAddr + nbp * 16 * ASTRIDE + BK[s]);
                mma_bf16(d[2 * nbp],     a0, bb[0], bb[2]);
                mma_bf16(d[2 * nbp + 1], a0, bb[1], bb[3]);
            }
        }

        // fold scores (D already = c0 - 2*dot) into per-slot min1/min2 keys
        uint32_t p0 = t1[0], p1 = t1[1];
        #pragma unroll
        for (int nb = 0; nb < 8; ++nb)
            #pragma unroll
            for (int j = 0; j < 4; ++j) {
                float sc = fminf(fmaxf(d[nb][j], 0.25f), 0.75f); // binding -> self-flag
                uint32_t key = __float_as_uint(sc) * 64u + KC
                             + (uint32_t)(nb * 8 + (j & 1));
                int sl = j >> 1;
                t2[sl] = min(t2[sl], max(t1[sl], key));
                t1[sl] = min(t1[sl], key);
            }
        if (t1[0] != p0) th[0] = h;
        if (t1[1] != p1) th[1] = h;
    }

    // merge across the 4 col-lanes (xor 1, 2); ties always flag -> order moot
    #pragma unroll
    for (int m = 1; m <= 2; m <<= 1) {
        #pragma unroll
        for (int sl = 0; sl < 2; ++sl) {
            uint32_t o1 = __shfl_xor_sync(~0u, t1[sl], m);
            int      ot = __shfl_xor_sync(~0u, th[sl], m);
            uint32_t o2 = __shfl_xor_sync(~0u, t2[sl], m);
            uint32_t n2 = min(min(t2[sl], o2), max(t1[sl], o1));
            if (o1 < t1[sl]) { t1[sl] = o1; th[sl] = ot; }
            t2[sl] = n2;
        }
    }
    if ((lane & 3) == 0) {
        #pragma unroll
        for (int sl = 0; sl < 2; ++sl) {
            int row = w * 16 + (lane >> 2) + sl * 8;
            int k = th[sl] * 64 + (int)(t1[sl] & 63u);
            float s1 = __uint_as_float(SBASE + (t1[sl] >> 6));
            float s2 = __uint_as_float(SBASE + (t2[sl] >> 6));
            bool fl = (s2 - s1) < W_MARGIN;
            sIdx[row] = fl ? -1 : k;
            if (fl) g_flag[atomicAdd(&g_nflag, 1)] = rowbase + row;
        }
    }
    __syncthreads();

    // fused output + loss for unflagged rows
    float lsum = 0.0f;
    #pragma unroll
    for (int i = 0; i < 8; ++i) {
        int e = tid + i * 256;
        int r = e >> 4, d4 = (e & 15) * 4;
        int k = sIdx[r];
        if (k >= 0) {
            float4 q  = __ldg((const float4*)(cb + (size_t)k * DIM + d4));
            float4 xv = __ldg((const float4*)(x + (size_t)(rowbase + r) * DIM + d4));
            *(float4*)(out + (size_t)(rowbase + r) * DIM + d4) = q;
            float a = q.x - xv.x, b = q.y - xv.y, c = q.z - xv.z, dd = q.w - xv.w;
            lsum += a * a + b * b + c * c + dd * dd;
        }
    }
    #pragma unroll
    for (int m = 16; m >= 1; m >>= 1)
        lsum += __shfl_xor_sync(0xffffffffu, lsum, m);
    float* sRed = (float*)(smx + SRED);
    if (lane == 0) sRed[w] = lsum;
    __syncthreads();
    if (tid < 8) {
        float v = sRed[tid];
        #pragma unroll
        for (int m = 4; m >= 1; m >>= 1)
            v += __shfl_xor_sync(0x000000ffu, v, m);
        if (tid == 0) atomicAdd(&g_loss, v);
    }
}

// ======== stage 2: exact bit-matched rescan of flagged rows + their output ========
__global__ __launch_bounds__(256) void vq_fix(const float* __restrict__ x,
                                              const float* __restrict__ cb,
                                              float* __restrict__ out) {
    __shared__ float sX[16 * 65];
    __shared__ float sE[128 * 65];
    __shared__ float sH[128];
    __shared__ float sXn[16];
    __shared__ int   sRow[16];
    __shared__ float sRed[8];
    const int tid = threadIdx.x, tx = tid & 15, ty = tid >> 4;
    const int nf = g_nflag;
    float lsum = 0.0f;

    for (int base = blockIdx.x * 16; base < nf; base += gridDim.x * 16) {
        int cnt = min(16, nf - base);
        __syncthreads();
        if (tid < 16) sRow[tid] = g_flag[base + min(tid, cnt - 1)];
        __syncthreads();
        {
            int r = tid >> 4, d = (tid & 15) * 4;
            float4 v = *(const float4*)(x + (size_t)sRow[r] * DIM + d);
            float* p = sX + r * 65 + d;
            p[0] = v.x; p[1] = v.y; p[2] = v.z; p[3] = v.w;
        }
        __syncthreads();
        if (tid < 16) {
            const float* p = sX + tid * 65;
            float s = 0.0f;
            #pragma unroll
            for (int i = 0; i < DIM; ++i)
                s = __fadd_rn(s, __fmul_rn(p[i], p[i]));
            sXn[tid] = s;
        }
        float bestv = 3.4e38f; int besti = 0;
        for (int t = 0; t < 8; ++t) {
            __syncthreads();
            #pragma unroll
            for (int i = 0; i < 8; ++i) {
                int e = tid + i * 256;
                int c = e >> 4, d = (e & 15) * 4;
                float4 v = *(const float4*)(cb + (size_t)(t * 128 + c) * DIM + d);
                float* p = sE + c * 65 + d;
                p[0] = v.x; p[1] = v.y; p[2] = v.z; p[3] = v.w;
            }
            if (tid < 128) sH[tid] = g_e[t * 128 + tid];
            __syncthreads();
            float acc[8];
            #pragma unroll
            for (int j = 0; j < 8; ++j) acc[j] = 0.0f;
            #pragma unroll 4
            for (int d = 0; d < DIM; ++d) {
                float xv = sX[ty * 65 + d];
                #pragma unroll
                for (int j = 0; j < 8; ++j) acc[j] += xv * sE[(tx + 16 * j) * 65 + d];
            }
            #pragma unroll
            for (int j = 0; j < 8; ++j) {
                int cg = tx + 16 * j;
                float dist = __fsub_rn(__fadd_rn(sXn[ty], sH[cg]),
                                       __fmul_rn(2.0f, acc[j]));
                if (dist < bestv) { bestv = dist; besti = t * 128 + cg; }
            }
        }
        #pragma unroll
        for (int m = 1; m < 16; m <<= 1) {
            float ov = __shfl_xor_sync(0xffffffffu, bestv, m);
            int   oi = __shfl_xor_sync(0xffffffffu, besti, m);
            if (ov < bestv || (ov == bestv && oi < besti)) { bestv = ov; besti = oi; }
        }
        // write this flagged row's output + loss (16 lanes x 4 dims)
        if (ty < cnt) {
            int d = tx * 4;
            float4 q = __ldg((const float4*)(cb + (size_t)besti * DIM + d));
            *(float4*)(out + (size_t)sRow[ty] * DIM + d) = q;
            const float* xp = sX + ty * 65 + d;
            float a = q.x - xp[0], b = q.y - xp[1], c = q.z - xp[2], dd = q.w - xp[3];
            lsum += a * a + b * b + c * c + dd * dd;
        }
    }
    // block loss reduce (threads that never looped contribute 0)
    #pragma unroll
    for (int m = 16; m >= 1; m >>= 1)
        lsum += __shfl_xor_sync(0xffffffffu, lsum, m);
    __syncthreads();
    if ((tid & 31) == 0) sRed[tid >> 5] = lsum;
    __syncthreads();
    if (tid < 8) {
        float v = sRed[tid];
        #pragma unroll
        for (int m = 4; m >= 1; m >>= 1)
            v += __shfl_xor_sync(0x000000ffu, v, m);
        if (tid == 0) atomicAdd(&g_loss, v);
    }
}

__global__ void vq_finish(float* out, int pos, float inv_n) {
    // vq_loss = codebook_loss + 0.25*commitment_loss; both equal mean((q-x)^2)
    out[pos] = 1.25f * g_loss * inv_n;
}

extern "C" void kernel_launch(void* const* d_in, const int* in_sizes, int n_in,
                              void* d_out, int out_size) {
    const float* x  = (const float*)d_in[0];
    const float* cb = (const float*)d_in[1];
    float* out = (float*)d_out;
    const int nrows = in_sizes[0] / DIM;       // 65536
    const int nblocks = nrows / 128;           // 512

    cudaFuncSetAttribute(vq_main, cudaFuncAttributeMaxDynamicSharedMemorySize,
                         SM_TOTAL);

    vq_prep<<<8, 128>>>(cb);
    vq_main<<<nblocks, 256, SM_TOTAL>>>(x, cb, out);
    vq_fix<<<96, 256>>>(x, cb, out);
    vq_finish<<<1, 1>>>(out, out_size - 1, 1.0f / (float)((size_t)nrows * DIM));
}